// round 1
// baseline (speedup 1.0000x reference)
#include <cuda_runtime.h>
#include <cstdint>

// out[b] = sum_{f,g} x[b,f] * Q[f,g] * x[b,g],  Q upper-triangular (incl diag).
// B = 131072, F = 512, fp32.
//
// Strategy: register-blocked "GEMM with fused reduce" in fp32 using packed
// fma.rn.f32x2 (2 MACs/issue), skipping k-tiles entirely below the diagonal.

#define F_DIM 512

constexpr int BM = 64;   // rows per CTA
constexpr int BN = 64;   // g-columns per tile
constexpr int BK = 32;   // f-depth per smem stage
constexpr int NTHREADS = 256;

typedef unsigned long long u64;

__device__ __forceinline__ u64 pack2(float lo, float hi) {
    u64 r; asm("mov.b64 %0, {%1, %2};" : "=l"(r) : "f"(lo), "f"(hi)); return r;
}
__device__ __forceinline__ void unpack2(u64 v, float& lo, float& hi) {
    asm("mov.b64 {%0, %1}, %2;" : "=f"(lo), "=f"(hi) : "l"(v));
}
__device__ __forceinline__ u64 ffma2(u64 a, u64 b, u64 c) {
    u64 d; asm("fma.rn.f32x2 %0, %1, %2, %3;" : "=l"(d) : "l"(a), "l"(b), "l"(c));
    return d;
}

__global__ __launch_bounds__(NTHREADS)
void bilinear_diag_kernel(const float* __restrict__ x,
                          const float* __restrict__ Q,
                          float* __restrict__ out)
{
    __shared__ float As[BK][BM];   // x tile, transposed: As[f][row]
    __shared__ u64   Bs[BK][BN];   // Q tile, each value splatted (v,v)

    const int tid  = threadIdx.x;
    const int tx   = tid & 15;     // g-column group
    const int ty   = tid >> 4;     // row group
    const int row0 = blockIdx.x * BM;

    float acc0 = 0.f, acc1 = 0.f, acc2 = 0.f, acc3 = 0.f;

    #pragma unroll 1
    for (int n = 0; n < F_DIM / BN; ++n) {
        const int g0 = n * BN;

        u64 c[2][4];
        #pragma unroll
        for (int p = 0; p < 2; ++p)
            #pragma unroll
            for (int j = 0; j < 4; ++j) c[p][j] = 0ull;

        // Triangular skip: Q[f][g] == 0 for f > g, so only f < (n+1)*BN matters.
        const int ktiles = (n + 1) * (BN / BK);

        #pragma unroll 1
        for (int kt = 0; kt < ktiles; ++kt) {
            const int f0 = kt * BK;
            __syncthreads();   // protect previous stage's smem reads

            // --- fill A (2048 floats = 512 float4; 2 per thread), transposed
            #pragma unroll
            for (int part = 0; part < 2; ++part) {
                int v  = part * 256 + tid;
                int r  = v >> 3;           // 0..63
                int fq = (v & 7) * 4;      // 0..28
                float4 t = *reinterpret_cast<const float4*>(
                    &x[(row0 + r) * F_DIM + f0 + fq]);
                As[fq + 0][r] = t.x;
                As[fq + 1][r] = t.y;
                As[fq + 2][r] = t.z;
                As[fq + 3][r] = t.w;
            }
            // --- fill B splatted (2048 floats; 2 float4 per thread)
            #pragma unroll
            for (int part = 0; part < 2; ++part) {
                int v  = part * 256 + tid;
                int f  = v >> 4;           // 0..31
                int gq = (v & 15) * 4;     // 0..60
                float4 t = *reinterpret_cast<const float4*>(
                    &Q[(f0 + f) * F_DIM + g0 + gq]);
                Bs[f][gq + 0] = pack2(t.x, t.x);
                Bs[f][gq + 1] = pack2(t.y, t.y);
                Bs[f][gq + 2] = pack2(t.z, t.z);
                Bs[f][gq + 3] = pack2(t.w, t.w);
            }
            __syncthreads();

            // --- inner product: 3x LDS.128 + 8x fma.f32x2 per k
            #pragma unroll
            for (int k = 0; k < BK; ++k) {
                ulonglong2 a   = *reinterpret_cast<const ulonglong2*>(&As[k][ty * 4]);
                ulonglong2 b01 = *reinterpret_cast<const ulonglong2*>(&Bs[k][tx * 4]);
                ulonglong2 b23 = *reinterpret_cast<const ulonglong2*>(&Bs[k][tx * 4 + 2]);
                c[0][0] = ffma2(a.x, b01.x, c[0][0]);
                c[0][1] = ffma2(a.x, b01.y, c[0][1]);
                c[0][2] = ffma2(a.x, b23.x, c[0][2]);
                c[0][3] = ffma2(a.x, b23.y, c[0][3]);
                c[1][0] = ffma2(a.y, b01.x, c[1][0]);
                c[1][1] = ffma2(a.y, b01.y, c[1][1]);
                c[1][2] = ffma2(a.y, b23.x, c[1][2]);
                c[1][3] = ffma2(a.y, b23.y, c[1][3]);
            }
        }

        // --- epilogue for this g-tile: acc[row] += C[row][g] * x[row][g]
        const int col = g0 + tx * 4;
        const int r   = row0 + ty * 4;
        float4 v0 = *reinterpret_cast<const float4*>(&x[(r + 0) * F_DIM + col]);
        float4 v1 = *reinterpret_cast<const float4*>(&x[(r + 1) * F_DIM + col]);
        float4 v2 = *reinterpret_cast<const float4*>(&x[(r + 2) * F_DIM + col]);
        float4 v3 = *reinterpret_cast<const float4*>(&x[(r + 3) * F_DIM + col]);
        float xa0[4] = {v0.x, v0.y, v0.z, v0.w};
        float xa1[4] = {v1.x, v1.y, v1.z, v1.w};
        float xa2[4] = {v2.x, v2.y, v2.z, v2.w};
        float xa3[4] = {v3.x, v3.y, v3.z, v3.w};
        #pragma unroll
        for (int j = 0; j < 4; ++j) {
            float lo, hi;
            unpack2(c[0][j], lo, hi);
            acc0 += lo * xa0[j];
            acc1 += hi * xa1[j];
            unpack2(c[1][j], lo, hi);
            acc2 += lo * xa2[j];
            acc3 += hi * xa3[j];
        }
    }

    // --- reduce over the 16 tx lanes (xor masks 8,4,2,1 stay within half-warp)
    #pragma unroll
    for (int m = 8; m >= 1; m >>= 1) {
        acc0 += __shfl_xor_sync(0xffffffffu, acc0, m);
        acc1 += __shfl_xor_sync(0xffffffffu, acc1, m);
        acc2 += __shfl_xor_sync(0xffffffffu, acc2, m);
        acc3 += __shfl_xor_sync(0xffffffffu, acc3, m);
    }
    if (tx == 0) {
        const int r = row0 + ty * 4;
        out[r + 0] = acc0;
        out[r + 1] = acc1;
        out[r + 2] = acc2;
        out[r + 3] = acc3;
    }
}

extern "C" void kernel_launch(void* const* d_in, const int* in_sizes, int n_in,
                              void* d_out, int out_size)
{
    const float* x = (const float*)d_in[0];   // [131072, 512]
    const float* Q = (const float*)d_in[1];   // [512, 512] upper-triangular
    float* out     = (float*)d_out;           // [131072]

    const int B = in_sizes[0] / F_DIM;        // 131072
    bilinear_diag_kernel<<<B / BM, NTHREADS>>>(x, Q, out);
}

// round 3
// speedup vs baseline: 6.1157x; 6.1157x over previous
#include <cuda_runtime.h>
#include <cuda_bf16.h>
#include <cstdint>

// out[b] = x_b^T Q x_b, B=131072, F=512, fp32, Q upper-triangular (incl diag).
// sm_100 base target (no tcgen05): use mma.sync.m16n8k16 bf16 with hi/lo split
// (3 products), triangular k-chunk skip, cp.async double-buffered B tiles,
// fused rowsum(Y .* X) epilogue.

#define F_DIM 512
#define BM 64          // rows per CTA
#define BN 64          // g-tile width
#define KC 64          // k-chunk depth
#define NTILES (F_DIM / BN)   // 8
#define NTHREADS 256

// device-global split/transposed Q: Qt[g][f] = Q[f][g], bf16 hi/lo
__device__ __nv_bfloat16 g_Qt_hi[F_DIM * F_DIM];
__device__ __nv_bfloat16 g_Qt_lo[F_DIM * F_DIM];

// dynamic smem layout
#define SM_A_HI 0                   // 64 rows x 1024B (512 bf16)  = 64KB
#define SM_A_LO 65536               // 64KB
#define SM_B    131072              // 2 stages x (hi 8KB + lo 8KB) = 32KB
#define SM_TOTAL 163840

__device__ __forceinline__ uint32_t smem_u32(const void* p) {
    uint32_t a;
    asm("{ .reg .u64 t; cvta.to.shared.u64 t, %1; cvt.u32.u64 %0, t; }" : "=r"(a) : "l"(p));
    return a;
}
__device__ __forceinline__ void ldsm4(uint32_t r[4], uint32_t addr) {
    asm volatile("ldmatrix.sync.aligned.m8n8.x4.shared.b16 {%0,%1,%2,%3}, [%4];"
                 : "=r"(r[0]), "=r"(r[1]), "=r"(r[2]), "=r"(r[3]) : "r"(addr));
}
__device__ __forceinline__ void mma_bf16(float d[4], const uint32_t a[4],
                                         uint32_t b0, uint32_t b1) {
    asm volatile(
        "mma.sync.aligned.m16n8k16.row.col.f32.bf16.bf16.f32 "
        "{%0,%1,%2,%3}, {%4,%5,%6,%7}, {%8,%9}, {%0,%1,%2,%3};"
        : "+f"(d[0]), "+f"(d[1]), "+f"(d[2]), "+f"(d[3])
        : "r"(a[0]), "r"(a[1]), "r"(a[2]), "r"(a[3]), "r"(b0), "r"(b1));
}
__device__ __forceinline__ void cpasync16(uint32_t dst, const void* src) {
    asm volatile("cp.async.cg.shared.global [%0], [%1], 16;" :: "r"(dst), "l"(src));
}
__device__ __forceinline__ void cp_commit() {
    asm volatile("cp.async.commit_group;" ::: "memory");
}
__device__ __forceinline__ void cp_wait1() {
    asm volatile("cp.async.wait_group 1;" ::: "memory");
}
__device__ __forceinline__ void cp_wait0() {
    asm volatile("cp.async.wait_group 0;" ::: "memory");
}

// ---------------- prep: split + transpose Q ----------------
__global__ void prep_q_kernel(const float* __restrict__ Q) {
    int i = blockIdx.x * blockDim.x + threadIdx.x;   // i = f*512 + g
    int f = i >> 9;
    int g = i & (F_DIM - 1);
    float v = Q[i];
    __nv_bfloat16 hi = __float2bfloat16(v);
    __nv_bfloat16 lo = __float2bfloat16(v - __bfloat162float(hi));
    g_Qt_hi[g * F_DIM + f] = hi;
    g_Qt_lo[g * F_DIM + f] = lo;
}

// ---------------- main kernel ----------------
__global__ __launch_bounds__(NTHREADS, 1)
void bilinear_hmma_kernel(const float* __restrict__ x, float* __restrict__ out) {
    extern __shared__ __align__(1024) char smem[];
    const uint32_t sbase = smem_u32(smem);
    const int tid  = threadIdx.x;
    const int lane = tid & 31;
    const int wid  = tid >> 5;
    const int wm   = wid & 3;    // 4 warps over M
    const int wn   = wid >> 2;   // 2 warps over N
    const int r0   = blockIdx.x * BM;

    // ---- prefetch B tile (n=0,c=0) into stage 0 ----
    {
        #pragma unroll
        for (int hl = 0; hl < 2; ++hl)
            #pragma unroll
            for (int rr = 0; rr < 2; ++rr) {
                int v = rr * NTHREADS + tid;
                int nrow = v >> 3, chunk = v & 7;
                const __nv_bfloat16* src =
                    (hl ? g_Qt_lo : g_Qt_hi) + (size_t)nrow * F_DIM + chunk * 8;
                uint32_t dst = sbase + SM_B + hl * 8192 + nrow * 128 +
                               ((chunk * 16) ^ ((nrow & 7) * 16));
                cpasync16(dst, src);
            }
        cp_commit();
    }

    // ---- load + split-convert full X row-block [64 x 512] into A_hi/A_lo ----
    #pragma unroll
    for (int it = 0; it < (BM * F_DIM / 4) / NTHREADS; ++it) {   // 32 iters
        int v = it * NTHREADS + tid;
        int row = v >> 7;                 // 0..63
        int k   = (v & 127) * 4;          // 0..508
        float4 t = *reinterpret_cast<const float4*>(
            &x[(size_t)(r0 + row) * F_DIM + k]);
        __nv_bfloat16 h0 = __float2bfloat16(t.x), h1 = __float2bfloat16(t.y);
        __nv_bfloat16 h2 = __float2bfloat16(t.z), h3 = __float2bfloat16(t.w);
        __nv_bfloat16 l0 = __float2bfloat16(t.x - __bfloat162float(h0));
        __nv_bfloat16 l1 = __float2bfloat16(t.y - __bfloat162float(h1));
        __nv_bfloat16 l2 = __float2bfloat16(t.z - __bfloat162float(h2));
        __nv_bfloat16 l3 = __float2bfloat16(t.w - __bfloat162float(h3));
        uint2 hv = make_uint2(
            (uint32_t)__bfloat16_as_ushort(h0) | ((uint32_t)__bfloat16_as_ushort(h1) << 16),
            (uint32_t)__bfloat16_as_ushort(h2) | ((uint32_t)__bfloat16_as_ushort(h3) << 16));
        uint2 lv = make_uint2(
            (uint32_t)__bfloat16_as_ushort(l0) | ((uint32_t)__bfloat16_as_ushort(l1) << 16),
            (uint32_t)__bfloat16_as_ushort(l2) | ((uint32_t)__bfloat16_as_ushort(l3) << 16));
        uint32_t kbyte = (uint32_t)k * 2;
        uint32_t off   = row * 1024 + (kbyte ^ ((row & 7) * 16));
        *reinterpret_cast<uint2*>(smem + SM_A_HI + off) = hv;
        *reinterpret_cast<uint2*>(smem + SM_A_LO + off) = lv;
    }

    // ---- per-thread ldmatrix address components ----
    const int a_row = wm * 16 + (lane & 15);
    const int a_seg = lane >> 4;
    const uint32_t a_base_hi = sbase + SM_A_HI + a_row * 1024;
    const uint32_t a_swz     = (a_row & 7) * 16;
    const uint32_t a_segoff  = a_seg * 16;

    const int b_row0 = wn * 32 + (lane & 15);        // pair 0
    const int b_row1 = b_row0 + 16;                  // pair 1
    const int b_seg  = lane >> 4;
    const uint32_t b_base0 = sbase + SM_B + b_row0 * 128;
    const uint32_t b_base1 = sbase + SM_B + b_row1 * 128;
    const uint32_t b_swz0  = (b_row0 & 7) * 16;
    const uint32_t b_swz1  = (b_row1 & 7) * 16;
    const uint32_t b_segoff = b_seg * 16;

    float d[4][4];
    #pragma unroll
    for (int j = 0; j < 4; ++j)
        #pragma unroll
        for (int q = 0; q < 4; ++q) d[j][q] = 0.f;

    float acc0 = 0.f, acc1 = 0.f;
    const int ep_row = wm * 16 + (lane >> 2);
    const float* xr0 = x + (size_t)(r0 + ep_row) * F_DIM;
    const float* xr1 = xr0 + (size_t)8 * F_DIM;
    const int ep_c   = wn * 32 + (lane & 3) * 2;

    int n = 0, c = 0;
    const int NIT = NTILES * (NTILES + 1) / 2;   // 36
    for (int it = 0; it < NIT; ++it) {
        // next (n,c) in triangular order
        int nn = (c < n) ? n : n + 1;
        int cc = (c < n) ? c + 1 : 0;

        // prefetch next B tile into the other stage
        if (it + 1 < NIT) {
            int stage = (it + 1) & 1;
            #pragma unroll
            for (int hl = 0; hl < 2; ++hl)
                #pragma unroll
                for (int rr = 0; rr < 2; ++rr) {
                    int v = rr * NTHREADS + tid;
                    int nrow = v >> 3, chunk = v & 7;
                    const __nv_bfloat16* src = (hl ? g_Qt_lo : g_Qt_hi) +
                        (size_t)(nn * BN + nrow) * F_DIM + cc * KC + chunk * 8;
                    uint32_t dst = sbase + SM_B + stage * 16384 + hl * 8192 +
                                   nrow * 128 + ((chunk * 16) ^ ((nrow & 7) * 16));
                    cpasync16(dst, src);
                }
            cp_commit();
            cp_wait1();
        } else {
            cp_wait0();
        }
        __syncthreads();

        // ---- MMA over this k-chunk (4 k16 steps, 3 passes) ----
        const uint32_t bst = (uint32_t)((it & 1) * 16384);
        #pragma unroll
        for (int kk = 0; kk < 4; ++kk) {
            const uint32_t a_off = (uint32_t)(c * 128 + kk * 32) + a_segoff;
            uint32_t ah[4], al[4];
            ldsm4(ah, a_base_hi + (a_off ^ a_swz));
            ldsm4(al, a_base_hi + 65536 + (a_off ^ a_swz));

            const uint32_t kb = (uint32_t)(kk * 32) + b_segoff;
            uint32_t bh0[4], bh1[4], bl0[4], bl1[4];
            ldsm4(bh0, b_base0 + bst + (kb ^ b_swz0));
            ldsm4(bh1, b_base1 + bst + (kb ^ b_swz1));
            ldsm4(bl0, b_base0 + bst + 8192 + (kb ^ b_swz0));
            ldsm4(bl1, b_base1 + bst + 8192 + (kb ^ b_swz1));

            // n-frags: j=0,1 from pair0 (regs {j, j+2}), j=2,3 from pair1
            mma_bf16(d[0], ah, bh0[0], bh0[2]);
            mma_bf16(d[1], ah, bh0[1], bh0[3]);
            mma_bf16(d[2], ah, bh1[0], bh1[2]);
            mma_bf16(d[3], ah, bh1[1], bh1[3]);
            mma_bf16(d[0], ah, bl0[0], bl0[2]);
            mma_bf16(d[1], ah, bl0[1], bl0[3]);
            mma_bf16(d[2], ah, bl1[0], bl1[2]);
            mma_bf16(d[3], ah, bl1[1], bl1[3]);
            mma_bf16(d[0], al, bh0[0], bh0[2]);
            mma_bf16(d[1], al, bh0[1], bh0[3]);
            mma_bf16(d[2], al, bh1[0], bh1[2]);
            mma_bf16(d[3], al, bh1[1], bh1[3]);
        }

        // ---- epilogue when this g-tile's k-loop is done (c == n) ----
        if (c == n) {
            const int cb = n * BN + ep_c;
            #pragma unroll
            for (int j = 0; j < 4; ++j) {
                float2 xa = *reinterpret_cast<const float2*>(xr0 + cb + j * 8);
                float2 xb = *reinterpret_cast<const float2*>(xr1 + cb + j * 8);
                acc0 += d[j][0] * xa.x + d[j][1] * xa.y;
                acc1 += d[j][2] * xb.x + d[j][3] * xb.y;
                d[j][0] = d[j][1] = d[j][2] = d[j][3] = 0.f;
            }
        }
        __syncthreads();   // stage consumed; next iter's prefetch may overwrite
        n = nn; c = cc;
    }

    // ---- final reduction: quad lanes, then across the 2 n-warps ----
    acc0 += __shfl_xor_sync(0xffffffffu, acc0, 1);
    acc0 += __shfl_xor_sync(0xffffffffu, acc0, 2);
    acc1 += __shfl_xor_sync(0xffffffffu, acc1, 1);
    acc1 += __shfl_xor_sync(0xffffffffu, acc1, 2);

    float* red = reinterpret_cast<float*>(smem);   // reuse A region
    __syncthreads();
    if ((lane & 3) == 0) {
        red[wn * 64 + ep_row]     = acc0;
        red[wn * 64 + ep_row + 8] = acc1;
    }
    __syncthreads();
    if (tid < BM) out[r0 + tid] = red[tid] + red[64 + tid];
}

extern "C" void kernel_launch(void* const* d_in, const int* in_sizes, int n_in,
                              void* d_out, int out_size) {
    const float* x = (const float*)d_in[0];   // [131072, 512]
    const float* Q = (const float*)d_in[1];   // [512, 512]
    float* out     = (float*)d_out;           // [131072]

    const int B = in_sizes[0] / F_DIM;

    cudaFuncSetAttribute(bilinear_hmma_kernel,
                         cudaFuncAttributeMaxDynamicSharedMemorySize, SM_TOTAL);

    prep_q_kernel<<<(F_DIM * F_DIM) / NTHREADS, NTHREADS>>>(Q);
    bilinear_hmma_kernel<<<B / BM, NTHREADS, SM_TOTAL>>>(x, out);
}

// round 5
// speedup vs baseline: 14.7105x; 2.4054x over previous
#include <cuda_runtime.h>
#include <cuda_fp16.h>
#include <cstdint>

// out[b] = x_b^T Q x_b, B=131072, F=512, fp32, Q upper-triangular (incl diag).
// Single-pass fp16 HMMA (m16n8k16.f32.f16.f16.f32), triangular k-chunk skip,
// cp.async double-buffered B tiles, fused rowsum(Y .* X) epilogue.
// 96KB smem/CTA + <=128 regs => 2 CTAs/SM.

#define F_DIM 512
#define BM 64            // rows per CTA
#define BN 128           // g-tile width
#define KC 64            // k-chunk depth
#define NTHREADS 256

// device-global transposed Q in fp16: Qt[g][f] = (half)Q[f][g]
__device__ __half g_Qt[F_DIM * F_DIM];

// dynamic smem layout
#define SM_A     0                  // 64 rows x 1024B (512 fp16) = 64KB
#define SM_B     65536              // 2 stages x 16KB (128 n-rows x 128B)
#define SM_TOTAL 98304

__device__ __forceinline__ uint32_t h2u(__half2 h) {
    union { __half2 h; uint32_t u; } cvt;
    cvt.h = h;
    return cvt.u;
}
__device__ __forceinline__ uint32_t smem_u32(const void* p) {
    uint32_t a;
    asm("{ .reg .u64 t; cvta.to.shared.u64 t, %1; cvt.u32.u64 %0, t; }" : "=r"(a) : "l"(p));
    return a;
}
__device__ __forceinline__ void ldsm4(uint32_t r[4], uint32_t addr) {
    asm volatile("ldmatrix.sync.aligned.m8n8.x4.shared.b16 {%0,%1,%2,%3}, [%4];"
                 : "=r"(r[0]), "=r"(r[1]), "=r"(r[2]), "=r"(r[3]) : "r"(addr));
}
__device__ __forceinline__ void mma_fp16(float d[4], const uint32_t a[4],
                                         uint32_t b0, uint32_t b1) {
    asm volatile(
        "mma.sync.aligned.m16n8k16.row.col.f32.f16.f16.f32 "
        "{%0,%1,%2,%3}, {%4,%5,%6,%7}, {%8,%9}, {%0,%1,%2,%3};"
        : "+f"(d[0]), "+f"(d[1]), "+f"(d[2]), "+f"(d[3])
        : "r"(a[0]), "r"(a[1]), "r"(a[2]), "r"(a[3]), "r"(b0), "r"(b1));
}
__device__ __forceinline__ void cpasync16(uint32_t dst, const void* src) {
    asm volatile("cp.async.cg.shared.global [%0], [%1], 16;" :: "r"(dst), "l"(src));
}
__device__ __forceinline__ void cp_commit() {
    asm volatile("cp.async.commit_group;" ::: "memory");
}
__device__ __forceinline__ void cp_wait1() {
    asm volatile("cp.async.wait_group 1;" ::: "memory");
}
__device__ __forceinline__ void cp_wait0() {
    asm volatile("cp.async.wait_group 0;" ::: "memory");
}

// ---------------- prep: transpose + convert Q ----------------
__global__ void prep_q_kernel(const float* __restrict__ Q) {
    int i = blockIdx.x * blockDim.x + threadIdx.x;   // i = f*512 + g
    int f = i >> 9;
    int g = i & (F_DIM - 1);
    g_Qt[g * F_DIM + f] = __float2half(Q[i]);
}

// ---------------- main kernel ----------------
__global__ __launch_bounds__(NTHREADS, 2)
void bilinear_fp16_kernel(const float* __restrict__ x, float* __restrict__ out) {
    extern __shared__ __align__(1024) char smem[];
    const uint32_t sbase = smem_u32(smem);
    const int tid  = threadIdx.x;
    const int lane = tid & 31;
    const int wid  = tid >> 5;
    const int wm   = wid & 1;     // 2 warps over M (32 rows each)
    const int wn   = wid >> 1;    // 4 warps over N (32 cols each)
    const int r0   = blockIdx.x * BM;

    // ---- prefetch B tile (n=0, c=0) into stage 0 ----
    {
        #pragma unroll
        for (int rr = 0; rr < 4; ++rr) {
            int v = rr * NTHREADS + tid;
            int nrow = v >> 3, chunk = v & 7;
            const __half* src = g_Qt + (size_t)nrow * F_DIM + chunk * 8;
            uint32_t dst = sbase + SM_B + nrow * 128 +
                           ((chunk * 16) ^ ((nrow & 7) * 16));
            cpasync16(dst, src);
        }
        cp_commit();
    }

    // ---- convert X row-block [64 x 512] fp32 -> fp16 into A ----
    #pragma unroll
    for (int it = 0; it < (BM * F_DIM / 4) / NTHREADS; ++it) {   // 32 iters
        int v   = it * NTHREADS + tid;
        int row = v >> 7;                 // 0..63
        int k   = (v & 127) * 4;          // 0..508
        float4 t = *reinterpret_cast<const float4*>(
            &x[(size_t)(r0 + row) * F_DIM + k]);
        __half2 h01 = __floats2half2_rn(t.x, t.y);
        __half2 h23 = __floats2half2_rn(t.z, t.w);
        uint32_t kbyte = (uint32_t)k * 2;
        uint32_t off   = row * 1024 + (kbyte ^ ((row & 7) * 16));
        *reinterpret_cast<uint2*>(smem + SM_A + off) =
            make_uint2(h2u(h01), h2u(h23));
    }

    // ---- per-thread ldmatrix address components ----
    const int a_row        = wm * 32 + (lane & 15);
    const uint32_t a_base  = sbase + SM_A + a_row * 1024;
    const uint32_t a_swz   = (a_row & 7) * 16;
    const uint32_t a_seg   = (lane >> 4) * 16;

    const int b_row        = wn * 32 + (lane & 15);
    const uint32_t b_off0  = (uint32_t)(b_row * 128);
    const uint32_t b_off1  = b_off0 + 16 * 128;
    const uint32_t b_swz   = (b_row & 7) * 16;   // (b_row+16)&7 == b_row&7
    const uint32_t b_seg   = (lane >> 4) * 16;

    float d[2][4][4];
    #pragma unroll
    for (int mf = 0; mf < 2; ++mf)
        #pragma unroll
        for (int nj = 0; nj < 4; ++nj)
            #pragma unroll
            for (int q = 0; q < 4; ++q) d[mf][nj][q] = 0.f;

    float acc00 = 0.f, acc01 = 0.f, acc10 = 0.f, acc11 = 0.f;
    const int ep_r  = lane >> 2;          // 0..7
    const int ep_c2 = (lane & 3) * 2;

    int n = 0, c = 0;
    const int NIT = 20;   // sum over n of (n+1) k-chunks, chunks of 64 within 128-tiles
    for (int it = 0; it < NIT; ++it) {
        const int cmax = 2 * n + 1;
        const int nn = (c < cmax) ? n : n + 1;
        const int cc = (c < cmax) ? c + 1 : 0;

        // prefetch next B tile into other stage
        if (it + 1 < NIT) {
            const int stage = (it + 1) & 1;
            #pragma unroll
            for (int rr = 0; rr < 4; ++rr) {
                int v = rr * NTHREADS + tid;
                int nrow = v >> 3, chunk = v & 7;
                const __half* src = g_Qt +
                    (size_t)(nn * BN + nrow) * F_DIM + cc * KC + chunk * 8;
                uint32_t dst = sbase + SM_B + stage * 16384 + nrow * 128 +
                               ((chunk * 16) ^ ((nrow & 7) * 16));
                cpasync16(dst, src);
            }
            cp_commit();
            cp_wait1();
        } else {
            cp_wait0();
        }
        __syncthreads();

        const uint32_t bst = sbase + SM_B + (uint32_t)((it & 1) * 16384);
        #pragma unroll
        for (int kk = 0; kk < 4; ++kk) {
            const uint32_t akb = (uint32_t)(c * 128 + kk * 32) + a_seg;
            uint32_t a0[4], a1[4];
            ldsm4(a0, a_base + (akb ^ a_swz));
            ldsm4(a1, a_base + 16 * 1024 + (akb ^ a_swz));

            const uint32_t bkb = (uint32_t)(kk * 32) + b_seg;
            uint32_t b0[4], b1[4];
            ldsm4(b0, bst + b_off0 + (bkb ^ b_swz));
            ldsm4(b1, bst + b_off1 + (bkb ^ b_swz));

            mma_fp16(d[0][0], a0, b0[0], b0[2]);
            mma_fp16(d[0][1], a0, b0[1], b0[3]);
            mma_fp16(d[0][2], a0, b1[0], b1[2]);
            mma_fp16(d[0][3], a0, b1[1], b1[3]);
            mma_fp16(d[1][0], a1, b0[0], b0[2]);
            mma_fp16(d[1][1], a1, b0[1], b0[3]);
            mma_fp16(d[1][2], a1, b1[0], b1[2]);
            mma_fp16(d[1][3], a1, b1[1], b1[3]);
        }

        // ---- epilogue when this g-tile's k-loop finishes ----
        if (c == cmax) {
            const int cb = n * BN + wn * 32 + ep_c2;
            #pragma unroll
            for (int mf = 0; mf < 2; ++mf) {
                const size_t row = (size_t)(r0 + wm * 32 + mf * 16 + ep_r);
                const float* xr = x + row * F_DIM;
                float a0s = 0.f, a1s = 0.f;
                #pragma unroll
                for (int nj = 0; nj < 4; ++nj) {
                    float2 xa = *reinterpret_cast<const float2*>(xr + cb + nj * 8);
                    float2 xb = *reinterpret_cast<const float2*>(
                        xr + 8 * F_DIM + cb + nj * 8);
                    a0s += d[mf][nj][0] * xa.x + d[mf][nj][1] * xa.y;
                    a1s += d[mf][nj][2] * xb.x + d[mf][nj][3] * xb.y;
                    d[mf][nj][0] = d[mf][nj][1] = d[mf][nj][2] = d[mf][nj][3] = 0.f;
                }
                if (mf == 0) { acc00 += a0s; acc01 += a1s; }
                else         { acc10 += a0s; acc11 += a1s; }
            }
        }
        __syncthreads();   // stage consumed before next prefetch overwrites
        n = nn; c = cc;
    }

    // ---- reduce: quad lanes (cols), then across the 4 wn warps via smem ----
    acc00 += __shfl_xor_sync(0xffffffffu, acc00, 1);
    acc00 += __shfl_xor_sync(0xffffffffu, acc00, 2);
    acc01 += __shfl_xor_sync(0xffffffffu, acc01, 1);
    acc01 += __shfl_xor_sync(0xffffffffu, acc01, 2);
    acc10 += __shfl_xor_sync(0xffffffffu, acc10, 1);
    acc10 += __shfl_xor_sync(0xffffffffu, acc10, 2);
    acc11 += __shfl_xor_sync(0xffffffffu, acc11, 1);
    acc11 += __shfl_xor_sync(0xffffffffu, acc11, 2);

    float* red = reinterpret_cast<float*>(smem);   // reuse A region
    __syncthreads();
    if ((lane & 3) == 0) {
        const int rbase = wn * 64 + wm * 32 + ep_r;
        red[rbase + 0]  = acc00;   // mf=0, +0
        red[rbase + 8]  = acc01;   // mf=0, +8
        red[rbase + 16] = acc10;   // mf=1, +0
        red[rbase + 24] = acc11;   // mf=1, +8
    }
    __syncthreads();
    if (tid < BM)
        out[r0 + tid] = red[tid] + red[64 + tid] + red[128 + tid] + red[192 + tid];
}

extern "C" void kernel_launch(void* const* d_in, const int* in_sizes, int n_in,
                              void* d_out, int out_size) {
    const float* x = (const float*)d_in[0];   // [131072, 512]
    const float* Q = (const float*)d_in[1];   // [512, 512]
    float* out     = (float*)d_out;           // [131072]

    const int B = in_sizes[0] / F_DIM;

    cudaFuncSetAttribute(bilinear_fp16_kernel,
                         cudaFuncAttributeMaxDynamicSharedMemorySize, SM_TOTAL);

    prep_q_kernel<<<(F_DIM * F_DIM) / NTHREADS, NTHREADS>>>(Q);
    bilinear_fp16_kernel<<<B / BM, NTHREADS, SM_TOTAL>>>(x, out);
}

// round 6
// speedup vs baseline: 15.3873x; 1.0460x over previous
#include <cuda_runtime.h>
#include <cuda_fp16.h>
#include <cstdint>

// out[b] = x_b^T Q x_b, B=131072, F=512, fp32, Q upper-triangular (incl diag).
// fp16 HMMA, BM=128 x BN=128 CTA tile, warp tile 64x32 (1.5 wf/MMA),
// triangular k-chunk skip, cp.async double-buffered B, epilogue reads x (fp16)
// from the A smem tile => x read from DRAM exactly once.

#define F_DIM 512
#define BM 128           // rows per CTA
#define BN 128           // g-tile width
#define KC 64            // k-chunk depth
#define NTHREADS 256

// device-global transposed Q in fp16: Qt[g][f] = (half)Q[f][g]
__device__ __half g_Qt[F_DIM * F_DIM];

// dynamic smem layout
#define SM_A     0                  // 128 rows x 1024B (512 fp16) = 128KB
#define SM_B     131072             // 2 stages x 16KB (128 n-rows x 128B)
#define SM_TOTAL 163840

__device__ __forceinline__ uint32_t smem_u32(const void* p) {
    uint32_t a;
    asm("{ .reg .u64 t; cvta.to.shared.u64 t, %1; cvt.u32.u64 %0, t; }" : "=r"(a) : "l"(p));
    return a;
}
__device__ __forceinline__ void ldsm4(uint32_t r[4], uint32_t addr) {
    asm volatile("ldmatrix.sync.aligned.m8n8.x4.shared.b16 {%0,%1,%2,%3}, [%4];"
                 : "=r"(r[0]), "=r"(r[1]), "=r"(r[2]), "=r"(r[3]) : "r"(addr));
}
__device__ __forceinline__ void mma_fp16(float d[4], const uint32_t a[4],
                                         uint32_t b0, uint32_t b1) {
    asm volatile(
        "mma.sync.aligned.m16n8k16.row.col.f32.f16.f16.f32 "
        "{%0,%1,%2,%3}, {%4,%5,%6,%7}, {%8,%9}, {%0,%1,%2,%3};"
        : "+f"(d[0]), "+f"(d[1]), "+f"(d[2]), "+f"(d[3])
        : "r"(a[0]), "r"(a[1]), "r"(a[2]), "r"(a[3]), "r"(b0), "r"(b1));
}
__device__ __forceinline__ void cpasync16(uint32_t dst, const void* src) {
    asm volatile("cp.async.cg.shared.global [%0], [%1], 16;" :: "r"(dst), "l"(src));
}
__device__ __forceinline__ void cp_commit() {
    asm volatile("cp.async.commit_group;" ::: "memory");
}
__device__ __forceinline__ void cp_wait1() {
    asm volatile("cp.async.wait_group 1;" ::: "memory");
}
__device__ __forceinline__ void cp_wait0() {
    asm volatile("cp.async.wait_group 0;" ::: "memory");
}

// ---------------- prep: transpose + convert Q ----------------
__global__ void prep_q_kernel(const float* __restrict__ Q) {
    int i = blockIdx.x * blockDim.x + threadIdx.x;   // i = f*512 + g
    int f = i >> 9;
    int g = i & (F_DIM - 1);
    g_Qt[g * F_DIM + f] = __float2half(Q[i]);
}

// ---------------- main kernel ----------------
__global__ __launch_bounds__(NTHREADS, 1)
void bilinear_fp16_kernel(const float* __restrict__ x, float* __restrict__ out) {
    extern __shared__ __align__(1024) char smem[];
    const uint32_t sbase = smem_u32(smem);
    const int tid  = threadIdx.x;
    const int lane = tid & 31;
    const int wid  = tid >> 5;
    const int wm   = wid & 1;     // 2 warp-groups over M (64 rows each)
    const int wn   = wid >> 1;    // 4 warp-groups over N (32 cols each)
    const int r0   = blockIdx.x * BM;

    // ---- prefetch B tile (n=0, c=0) into stage 0 ----
    {
        #pragma unroll
        for (int rr = 0; rr < 4; ++rr) {
            int v = rr * NTHREADS + tid;
            int nrow = v >> 3, chunk = v & 7;
            const __half* src = g_Qt + (size_t)nrow * F_DIM + chunk * 8;
            uint32_t dst = sbase + SM_B + nrow * 128 +
                           ((chunk * 16) ^ ((nrow & 7) * 16));
            cpasync16(dst, src);
        }
        cp_commit();
    }

    // ---- convert X row-block [128 x 512] fp32 -> fp16 into A ----
    // 8-half (16B) granules: 8192 granules / 256 threads = 32 iters
    #pragma unroll
    for (int it = 0; it < 32; ++it) {
        int v   = it * NTHREADS + tid;
        int row = v >> 6;                 // 0..127
        int k   = (v & 63) * 8;           // 0..504
        const float* xp = &x[(size_t)(r0 + row) * F_DIM + k];
        float4 t0 = *reinterpret_cast<const float4*>(xp);
        float4 t1 = *reinterpret_cast<const float4*>(xp + 4);
        __half2 h0 = __floats2half2_rn(t0.x, t0.y);
        __half2 h1 = __floats2half2_rn(t0.z, t0.w);
        __half2 h2 = __floats2half2_rn(t1.x, t1.y);
        __half2 h3 = __floats2half2_rn(t1.z, t1.w);
        union { __half2 h[4]; uint4 u; } cvt;
        cvt.h[0] = h0; cvt.h[1] = h1; cvt.h[2] = h2; cvt.h[3] = h3;
        uint32_t off = row * 1024 + (((uint32_t)k * 2) ^ ((row & 7) * 16));
        *reinterpret_cast<uint4*>(smem + SM_A + off) = cvt.u;
    }

    // ---- ldmatrix address components ----
    const uint32_t a_swz = (lane & 7) * 16;
    uint32_t a_base[4];
    #pragma unroll
    for (int j = 0; j < 4; ++j)
        a_base[j] = sbase + SM_A + (wm * 64 + j * 16 + (lane & 15)) * 1024;
    const uint32_t a_seg = (lane >> 4) * 16;

    const int b_row       = wn * 32 + (lane & 15);
    const uint32_t b_off0 = (uint32_t)(b_row * 128);
    const uint32_t b_off1 = b_off0 + 16 * 128;
    const uint32_t b_swz  = (b_row & 7) * 16;
    const uint32_t b_seg  = (lane >> 4) * 16;

    float d[4][4][4];     // [mf][nj][reg]
    #pragma unroll
    for (int mf = 0; mf < 4; ++mf)
        #pragma unroll
        for (int nj = 0; nj < 4; ++nj)
            #pragma unroll
            for (int q = 0; q < 4; ++q) d[mf][nj][q] = 0.f;

    float acc[4][2];      // [mf][row-group], per-thread partial sums
    #pragma unroll
    for (int mf = 0; mf < 4; ++mf) { acc[mf][0] = 0.f; acc[mf][1] = 0.f; }

    const int ep_r  = lane >> 2;          // 0..7
    const int ep_c2 = (lane & 3) * 2;

    int n = 0, c = 0;
    const int NIT = 20;
    for (int it = 0; it < NIT; ++it) {
        const int cmax = 2 * n + 1;
        const int nn = (c < cmax) ? n : n + 1;
        const int cc = (c < cmax) ? c + 1 : 0;

        // prefetch next B tile into other stage
        if (it + 1 < NIT) {
            const int stage = (it + 1) & 1;
            #pragma unroll
            for (int rr = 0; rr < 4; ++rr) {
                int v = rr * NTHREADS + tid;
                int nrow = v >> 3, chunk = v & 7;
                const __half* src = g_Qt +
                    (size_t)(nn * BN + nrow) * F_DIM + cc * KC + chunk * 8;
                uint32_t dst = sbase + SM_B + stage * 16384 + nrow * 128 +
                               ((chunk * 16) ^ ((nrow & 7) * 16));
                cpasync16(dst, src);
            }
            cp_commit();
            cp_wait1();
        } else {
            cp_wait0();
        }
        __syncthreads();

        const uint32_t bst = sbase + SM_B + (uint32_t)((it & 1) * 16384);
        #pragma unroll
        for (int kk = 0; kk < 4; ++kk) {
            const uint32_t akb = (uint32_t)(c * 128 + kk * 32) + a_seg;
            uint32_t a[4][4];
            #pragma unroll
            for (int j = 0; j < 4; ++j)
                ldsm4(a[j], a_base[j] + (akb ^ a_swz));

            const uint32_t bkb = (uint32_t)(kk * 32) + b_seg;
            uint32_t b0[4], b1[4];
            ldsm4(b0, bst + b_off0 + (bkb ^ b_swz));
            ldsm4(b1, bst + b_off1 + (bkb ^ b_swz));

            #pragma unroll
            for (int mf = 0; mf < 4; ++mf) {
                mma_fp16(d[mf][0], a[mf], b0[0], b0[2]);
                mma_fp16(d[mf][1], a[mf], b0[1], b0[3]);
                mma_fp16(d[mf][2], a[mf], b1[0], b1[2]);
                mma_fp16(d[mf][3], a[mf], b1[1], b1[3]);
            }
        }

        // ---- epilogue when this g-tile's k-loop finishes: x from smem (fp16)
        if (c == cmax) {
            #pragma unroll
            for (int mf = 0; mf < 4; ++mf) {
                #pragma unroll
                for (int rg = 0; rg < 2; ++rg) {
                    const int row = wm * 64 + mf * 16 + rg * 8 + ep_r;
                    const uint32_t rbase = (uint32_t)(row * 1024);
                    const uint32_t rswz  = (row & 7) * 16;
                    float s = 0.f;
                    #pragma unroll
                    for (int nj = 0; nj < 4; ++nj) {
                        const int col = n * BN + wn * 32 + nj * 8 + ep_c2;
                        uint32_t off = rbase + (((uint32_t)col * 2) ^ rswz);
                        __half2 xh = *reinterpret_cast<const __half2*>(
                            smem + SM_A + off);
                        float2 xf = __half22float2(xh);
                        s += d[mf][nj][rg * 2 + 0] * xf.x +
                             d[mf][nj][rg * 2 + 1] * xf.y;
                        d[mf][nj][rg * 2 + 0] = 0.f;
                        d[mf][nj][rg * 2 + 1] = 0.f;
                    }
                    acc[mf][rg] += s;
                }
            }
        }
        __syncthreads();   // stage consumed before next prefetch overwrites
        n = nn; c = cc;
    }

    // ---- reduce: quad lanes (cols), then across the 4 wn warps via smem ----
    #pragma unroll
    for (int mf = 0; mf < 4; ++mf)
        #pragma unroll
        for (int rg = 0; rg < 2; ++rg) {
            acc[mf][rg] += __shfl_xor_sync(0xffffffffu, acc[mf][rg], 1);
            acc[mf][rg] += __shfl_xor_sync(0xffffffffu, acc[mf][rg], 2);
        }

    float* red = reinterpret_cast<float*>(smem + SM_B);   // reuse B region
    if ((lane & 3) == 0) {
        #pragma unroll
        for (int mf = 0; mf < 4; ++mf)
            #pragma unroll
            for (int rg = 0; rg < 2; ++rg) {
                const int row = wm * 64 + mf * 16 + rg * 8 + ep_r;
                red[wn * BM + row] = acc[mf][rg];
            }
    }
    __syncthreads();
    if (tid < BM)
        out[r0 + tid] = red[tid] + red[BM + tid] +
                        red[2 * BM + tid] + red[3 * BM + tid];
}

extern "C" void kernel_launch(void* const* d_in, const int* in_sizes, int n_in,
                              void* d_out, int out_size) {
    const float* x = (const float*)d_in[0];   // [131072, 512]
    const float* Q = (const float*)d_in[1];   // [512, 512]
    float* out     = (float*)d_out;           // [131072]

    const int B = in_sizes[0] / F_DIM;

    cudaFuncSetAttribute(bilinear_fp16_kernel,
                         cudaFuncAttributeMaxDynamicSharedMemorySize, SM_TOTAL);

    prep_q_kernel<<<(F_DIM * F_DIM) / NTHREADS, NTHREADS>>>(Q);
    bilinear_fp16_kernel<<<B / BM, NTHREADS, SM_TOTAL>>>(x, out);
}